// round 1
// baseline (speedup 1.0000x reference)
#include <cuda_runtime.h>
#include <cuda_bf16.h>
#include <math.h>

// Problem constants (fixed by the reference)
#define DIMN   2048
#define BATCH  4
#define LQ     4096
#define KC     576
#define KT     (KC + LQ)      // 4672 total keys per batch

// ---------------------------------------------------------------------------
// Scratch (static __device__ arrays — no allocation allowed)
// ---------------------------------------------------------------------------
__device__ float g_q    [(size_t)BATCH * LQ * DIMN];   // 134 MB
__device__ float g_kfull[(size_t)BATCH * KT * DIMN];   // 153 MB (cached + new)
__device__ float g_vfull[(size_t)BATCH * KT * DIMN];   // 153 MB
__device__ float g_s    [(size_t)BATCH * LQ * KT];     // 306 MB scores/weights
__device__ float g_att  [(size_t)BATCH * LQ * DIMN];   // 134 MB

// ---------------------------------------------------------------------------
// f32x2 packed-FMA helpers (sm_100+/sm_103a)
// ---------------------------------------------------------------------------
__device__ __forceinline__ unsigned long long pack_dup(float x) {
    unsigned long long r;
    asm("mov.b64 %0, {%1, %1};" : "=l"(r) : "f"(x));
    return r;
}
__device__ __forceinline__ void unpack2(unsigned long long v, float& x, float& y) {
    asm("mov.b64 {%0, %1}, %2;" : "=f"(x), "=f"(y) : "l"(v));
}
__device__ __forceinline__ void fma2(unsigned long long& d,
                                     unsigned long long a,
                                     unsigned long long b) {
    asm("fma.rn.f32x2 %0, %1, %2, %0;" : "+l"(d) : "l"(a), "l"(b));
}

// ---------------------------------------------------------------------------
// Tiled GEMM, 128x128 tile, BK=8, 256 threads, 8x8 per thread (as 8x4 f32x2).
//   TRANSB=true :  C[M,N] = alpha * A[M,K] @ B[N,K]^T + bias
//   TRANSB=false:  C[M,N] = alpha * A[M,K] @ B[K,N]   + bias
// A rows (M) must be a multiple of 128 and K a multiple of 8 (true for all
// launches here). N edge handled by predication. blockIdx.z selects batch via
// the element strides sA/sB/sC.
// Inner loop uses packed fma.rn.f32x2: A is stored DUPLICATED in smem so each
// LDS.64 yields {a,a}; B pairs alias directly out of LDS.128.
// ---------------------------------------------------------------------------
#define BM  128
#define BN  128
#define BKK 8

template<bool TRANSB>
__global__ __launch_bounds__(256, 2)
void gemm_kernel(const float* __restrict__ Ag, const float* __restrict__ Bg,
                 const float* __restrict__ bias, float* __restrict__ Cg,
                 int M, int N, int K, float alpha,
                 long long sA, long long sB, long long sC)
{
    const float* A = Ag + (long long)blockIdx.z * sA;
    const float* B = Bg + (long long)blockIdx.z * sB;
    float*       C = Cg + (long long)blockIdx.z * sC;

    __shared__ float AsD[BKK][2 * BM + 4];  // duplicated A, stride 260 (8B-aligned rows)
    __shared__ float Bs [BKK][BN + 4];      // stride 132 (16B-aligned rows)

    const int tid  = threadIdx.x;
    const int tx   = tid & 15;       // 0..15  -> N micro-tile
    const int ty   = tid >> 4;       // 0..15  -> M micro-tile
    const int row0 = blockIdx.y * BM;
    const int col0 = blockIdx.x * BN;

    // global->smem load mapping (NT path: both A and B are [rows, K])
    const int lr = tid >> 1;         // 0..127 row within tile
    const int lc = (tid & 1) << 2;   // k offset {0,4}
    // NN path B mapping: [K, N] tile of 8 x 128
    const int bkr  = tid >> 5;           // 0..7  k row
    const int bcol = (tid & 31) << 2;    // 0..124 col (float4)

    unsigned long long acc[8][4];
#pragma unroll
    for (int i = 0; i < 8; i++)
#pragma unroll
        for (int j = 0; j < 4; j++) acc[i][j] = 0ull;

    for (int k0 = 0; k0 < K; k0 += BKK) {
        // ---- global loads into registers
        float4 av = *reinterpret_cast<const float4*>(
            &A[(long long)(row0 + lr) * K + (k0 + lc)]);
        float4 bv = make_float4(0.f, 0.f, 0.f, 0.f);
        if (TRANSB) {
            if (col0 + lr < N)
                bv = *reinterpret_cast<const float4*>(
                    &B[(long long)(col0 + lr) * K + (k0 + lc)]);
        } else {
            if (col0 + bcol < N)
                bv = *reinterpret_cast<const float4*>(
                    &B[(long long)(k0 + bkr) * N + (col0 + bcol)]);
        }

        __syncthreads();  // previous tile fully consumed

        // ---- store A duplicated: AsD[k][2r] = AsD[k][2r+1] = a
        *reinterpret_cast<unsigned long long*>(&AsD[lc + 0][2 * lr]) = pack_dup(av.x);
        *reinterpret_cast<unsigned long long*>(&AsD[lc + 1][2 * lr]) = pack_dup(av.y);
        *reinterpret_cast<unsigned long long*>(&AsD[lc + 2][2 * lr]) = pack_dup(av.z);
        *reinterpret_cast<unsigned long long*>(&AsD[lc + 3][2 * lr]) = pack_dup(av.w);
        if (TRANSB) {
            Bs[lc + 0][lr] = bv.x;
            Bs[lc + 1][lr] = bv.y;
            Bs[lc + 2][lr] = bv.z;
            Bs[lc + 3][lr] = bv.w;
        } else {
            *reinterpret_cast<float4*>(&Bs[bkr][bcol]) = bv;
        }

        __syncthreads();

        // ---- compute
#pragma unroll
        for (int kk = 0; kk < BKK; kk++) {
            unsigned long long aa[8];
#pragma unroll
            for (int i = 0; i < 8; i++)
                aa[i] = *reinterpret_cast<const unsigned long long*>(
                    &AsD[kk][ty * 16 + 2 * i]);
            double2 b01 = *reinterpret_cast<const double2*>(&Bs[kk][tx * 8]);
            double2 b23 = *reinterpret_cast<const double2*>(&Bs[kk][tx * 8 + 4]);
            unsigned long long bb[4];
            bb[0] = __double_as_longlong(b01.x);
            bb[1] = __double_as_longlong(b01.y);
            bb[2] = __double_as_longlong(b23.x);
            bb[3] = __double_as_longlong(b23.y);
#pragma unroll
            for (int i = 0; i < 8; i++)
#pragma unroll
                for (int j = 0; j < 4; j++)
                    fma2(acc[i][j], aa[i], bb[j]);
        }
    }

    // ---- epilogue
#pragma unroll
    for (int i = 0; i < 8; i++) {
        const int row = row0 + ty * 8 + i;
#pragma unroll
        for (int j = 0; j < 4; j++) {
            const int col = col0 + tx * 8 + 2 * j;
            if (col < N) {  // N is always even -> pair check collapses
                float x, y;
                unpack2(acc[i][j], x, y);
                x *= alpha; y *= alpha;
                if (bias) { x += bias[col]; y += bias[col + 1]; }
                *reinterpret_cast<float2*>(&C[(long long)row * N + col]) =
                    make_float2(x, y);
            }
        }
    }
}

// ---------------------------------------------------------------------------
// Copy cached K/V into the front of the full K/V buffers
// ---------------------------------------------------------------------------
__global__ void copy_cached_kernel(const float* __restrict__ ck,
                                   const float* __restrict__ cv)
{
    const int per   = KC * DIMN / 4;          // float4 per batch = 294912
    const int total = BATCH * per;            // 1179648
    int idx = blockIdx.x * blockDim.x + threadIdx.x;
    if (idx >= total) return;
    int b = idx / per;
    int r = idx - b * per;
    long long dst = (long long)b * (KT * DIMN / 4) + r;
    reinterpret_cast<float4*>(g_kfull)[dst] = reinterpret_cast<const float4*>(ck)[idx];
    reinterpret_cast<float4*>(g_vfull)[dst] = reinterpret_cast<const float4*>(cv)[idx];
}

// ---------------------------------------------------------------------------
// Row softmax with analytic causal mask: row q sees columns [0, 576+q+1),
// masked columns are written as 0 so the following NN GEMM is plain dense.
// ---------------------------------------------------------------------------
__global__ void softmax_kernel(float* __restrict__ S, float scale)
{
    const int q = blockIdx.x;   // 0..LQ-1
    const int b = blockIdx.y;
    float* row = S + ((long long)b * LQ + q) * KT;
    const int valid = KC + q + 1;     // <= KT
    const int tid = threadIdx.x;
    __shared__ float red[256];

    // pass 1: max of scaled scores
    float m = -1e30f;
    for (int c = tid; c < valid; c += 256) m = fmaxf(m, row[c] * scale);
    red[tid] = m;
    __syncthreads();
    for (int s = 128; s > 0; s >>= 1) {
        if (tid < s) red[tid] = fmaxf(red[tid], red[tid + s]);
        __syncthreads();
    }
    m = red[0];
    __syncthreads();

    // pass 2: sum of exp
    float sum = 0.f;
    for (int c = tid; c < valid; c += 256) sum += expf(row[c] * scale - m);
    red[tid] = sum;
    __syncthreads();
    for (int s = 128; s > 0; s >>= 1) {
        if (tid < s) red[tid] += red[tid + s];
        __syncthreads();
    }
    const float inv = 1.f / red[0];
    __syncthreads();

    // pass 3: write normalized weights, zeros beyond the causal frontier
    for (int c = tid; c < KT; c += 256)
        row[c] = (c < valid) ? expf(row[c] * scale - m) * inv : 0.f;
}

// ---------------------------------------------------------------------------
// kernel_launch — graph-capturable, allocation-free
// ---------------------------------------------------------------------------
extern "C" void kernel_launch(void* const* d_in, const int* in_sizes, int n_in,
                              void* d_out, int out_size)
{
    const float* chunk    = (const float*)d_in[0];
    const float* cached_k = (const float*)d_in[1];
    const float* cached_v = (const float*)d_in[2];
    // d_in[3] = cached_positions, then (possibly) total_seen — both unused:
    // every cached position < every new query position, so the mask is
    // analytic. Locate Wq robustly by size in case scalar inputs are skipped.
    int wi = 3;
    while (wi < n_in && in_sizes[wi] != DIMN * DIMN) wi++;
    const float* Wq = (const float*)d_in[wi + 0];
    const float* bq = (const float*)d_in[wi + 1];
    const float* Wk = (const float*)d_in[wi + 2];
    const float* bk = (const float*)d_in[wi + 3];
    const float* Wv = (const float*)d_in[wi + 4];
    const float* bv = (const float*)d_in[wi + 5];
    const float* Wo = (const float*)d_in[wi + 6];
    const float* bo = (const float*)d_in[wi + 7];
    float* out = (float*)d_out;

    float *pq, *pkf, *pvf, *ps, *patt;
    cudaGetSymbolAddress((void**)&pq,   g_q);
    cudaGetSymbolAddress((void**)&pkf,  g_kfull);
    cudaGetSymbolAddress((void**)&pvf,  g_vfull);
    cudaGetSymbolAddress((void**)&ps,   g_s);
    cudaGetSymbolAddress((void**)&patt, g_att);

    const float scale = (float)(1.0 / sqrt((double)DIMN));
    const dim3 blk(256);

    // 1) cached K/V -> front of full K/V
    copy_cached_kernel<<<(BATCH * KC * DIMN / 4 + 255) / 256, 256>>>(cached_k, cached_v);

    // 2) Q projection: [B*L, D] @ Wq^T + bq (batch folded into M)
    gemm_kernel<true><<<dim3(DIMN / BN, (BATCH * LQ) / BM, 1), blk>>>(
        chunk, Wq, bq, pq, BATCH * LQ, DIMN, DIMN, 1.f, 0, 0, 0);

    // 3) K projection -> rows [KC, KT) of g_kfull, per batch
    gemm_kernel<true><<<dim3(DIMN / BN, LQ / BM, BATCH), blk>>>(
        chunk, Wk, bk, pkf + (long long)KC * DIMN, LQ, DIMN, DIMN, 1.f,
        (long long)LQ * DIMN, 0, (long long)KT * DIMN);

    // 4) V projection -> rows [KC, KT) of g_vfull
    gemm_kernel<true><<<dim3(DIMN / BN, LQ / BM, BATCH), blk>>>(
        chunk, Wv, bv, pvf + (long long)KC * DIMN, LQ, DIMN, DIMN, 1.f,
        (long long)LQ * DIMN, 0, (long long)KT * DIMN);

    // 5) S = q @ k_full^T  (scale folded into softmax)
    gemm_kernel<true><<<dim3((KT + BN - 1) / BN, LQ / BM, BATCH), blk>>>(
        pq, pkf, nullptr, ps, LQ, KT, DIMN, 1.f,
        (long long)LQ * DIMN, (long long)KT * DIMN, (long long)LQ * KT);

    // 6) masked softmax (writes zeros beyond the causal frontier)
    softmax_kernel<<<dim3(LQ, BATCH), 256>>>(ps, scale);

    // 7) attended = W @ v_full  (NN)
    gemm_kernel<false><<<dim3(DIMN / BN, LQ / BM, BATCH), blk>>>(
        ps, pvf, nullptr, patt, LQ, DIMN, KT, 1.f,
        (long long)LQ * KT, (long long)KT * DIMN, (long long)LQ * DIMN);

    // 8) output projection: attended @ Wo^T + bo (batch folded into M)
    gemm_kernel<true><<<dim3(DIMN / BN, (BATCH * LQ) / BM, 1), blk>>>(
        patt, Wo, bo, out, BATCH * LQ, DIMN, DIMN, 1.f, 0, 0, 0);
}